// round 5
// baseline (speedup 1.0000x reference)
#include <cuda_runtime.h>

#define N_MOLS  32768
#define N_ATOMS 4194304
#define THREADS 256
#define N_TILES (N_ATOMS / 4 / THREADS)   // 4096 tiles of 1024 atoms
#define GRID    1184                       // 148 SMs * 8 resident blocks

__global__ void zero_energy_kernel(float4* __restrict__ energy4) {
    int i = blockIdx.x * blockDim.x + threadIdx.x;   // N_MOLS/4 = 8192 threads
    energy4[i] = make_float4(0.f, 0.f, 0.f, 0.f);
}

__device__ __forceinline__ float tanh_approx(float x) {
    float y;
    asm("tanh.approx.f32 %0, %1;" : "=f"(y) : "f"(x));
    return y;
}

__global__ __launch_bounds__(THREADS, 8) void sumpool_kernel(
    const float4* __restrict__ xyz4,     // N_ATOMS*3 floats viewed as float4
    const int4*   __restrict__ ids4,     // N_ATOMS ints viewed as int4
    const float*  __restrict__ w,        // 3 floats
    float*        __restrict__ energy,   // N_MOLS
    float4*       __restrict__ grad4)    // N_ATOMS*3 floats viewed as float4
{
    const int lane = threadIdx.x & 31;

    const float w0 = __ldg(w + 0);
    const float w1 = __ldg(w + 1);
    const float w2 = __ldg(w + 2);

    for (int tile = blockIdx.x; tile < N_TILES; tile += GRID) {
        const int tid = tile * THREADS + threadIdx.x;

        // 4 atoms = 3 coalesced float4 loads + 1 int4 (front-batched)
        const float4 a = xyz4[tid * 3 + 0];
        const float4 b = xyz4[tid * 3 + 1];
        const float4 c = xyz4[tid * 3 + 2];
        const int4  id = ids4[tid];

        // atom k coords: atom0: a.x a.y a.z | atom1: a.w b.x b.y
        //                atom2: b.z b.w c.x | atom3: c.y c.z c.w
        const float t0 = tanh_approx(a.x * w0 + a.y * w1 + a.z * w2);
        const float t1 = tanh_approx(a.w * w0 + b.x * w1 + b.y * w2);
        const float t2 = tanh_approx(b.z * w0 + b.w * w1 + c.x * w2);
        const float t3 = tanh_approx(c.y * w0 + c.z * w1 + c.w * w2);

        const float g0 = 1.0f - t0 * t0;
        const float g1 = 1.0f - t1 * t1;
        const float g2 = 1.0f - t2 * t2;
        const float g3 = 1.0f - t3 * t3;

        grad4[tid * 3 + 0] = make_float4(g0 * w0, g0 * w1, g0 * w2, g1 * w0);
        grad4[tid * 3 + 1] = make_float4(g1 * w1, g1 * w2, g2 * w0, g2 * w1);
        grad4[tid * 3 + 2] = make_float4(g2 * w2, g3 * w0, g3 * w1, g3 * w2);

        // ---- segment sum of t0..t3 over sorted ids ----
        int   cur = id.x;
        float s   = t0;
        if (id.y == cur) { s += t1; } else { atomicAdd(&energy[cur], s); cur = id.y; s = t1; }
        if (id.z == cur) { s += t2; } else { atomicAdd(&energy[cur], s); cur = id.z; s = t2; }
        if (id.w == cur) { s += t3; } else { atomicAdd(&energy[cur], s); cur = id.w; s = t3; }

        // warp-level segmented reduction (ids sorted => equal-id lanes contiguous)
        #pragma unroll
        for (int off = 1; off < 32; off <<= 1) {
            const float v   = __shfl_down_sync(0xffffffffu, s,   off);
            const int   oid = __shfl_down_sync(0xffffffffu, cur, off);
            if (lane + off < 32 && oid == cur) s += v;
        }
        const int prev = __shfl_up_sync(0xffffffffu, cur, 1);
        if (lane == 0 || prev != cur) {
            atomicAdd(&energy[cur], s);   // run leader flushes whole-run tail sum
        }
    }
}

extern "C" void kernel_launch(void* const* d_in, const int* in_sizes, int n_in,
                              void* d_out, int out_size) {
    const float4* xyz4 = (const float4*)d_in[0];
    const int4*   ids4 = (const int4*)d_in[1];
    const float*  w    = (const float*)d_in[2];

    float* energy = (float*)d_out;                      // [N_MOLS]
    float4* grad4 = (float4*)((float*)d_out + N_MOLS);  // [N_ATOMS*3] floats

    zero_energy_kernel<<<(N_MOLS / 4) / 256, 256>>>((float4*)energy);
    sumpool_kernel<<<GRID, THREADS>>>(xyz4, ids4, w, energy, grad4);
}

// round 6
// speedup vs baseline: 1.1716x; 1.1716x over previous
#include <cuda_runtime.h>

#define N_MOLS  32768
#define N_ATOMS 4194304
#define THREADS 256
// 4 atoms per thread
#define N_THREADS_TOTAL (N_ATOMS / 4)
#define N_BLOCKS (N_THREADS_TOTAL / THREADS)

__global__ void zero_energy_kernel(float4* __restrict__ energy4) {
    int i = blockIdx.x * blockDim.x + threadIdx.x;   // N_MOLS/4 = 8192 threads
    energy4[i] = make_float4(0.f, 0.f, 0.f, 0.f);
    // Signal dependent kernel it may begin launching (its gridDependencySynchronize
    // still guarantees our stores are visible before it consumes them).
    cudaTriggerProgrammaticLaunchCompletion();
}

__device__ __forceinline__ float tanh_approx(float x) {
    float y;
    asm("tanh.approx.f32 %0, %1;" : "=f"(y) : "f"(x));
    return y;
}

__global__ __launch_bounds__(THREADS) void sumpool_kernel(
    const float4* __restrict__ xyz4,     // N_ATOMS*3 floats viewed as float4
    const int4*   __restrict__ ids4,     // N_ATOMS ints viewed as int4
    const float*  __restrict__ w,        // 3 floats
    float*        __restrict__ energy,   // N_MOLS
    float4*       __restrict__ grad4)    // N_ATOMS*3 floats viewed as float4
{
    const int tid  = blockIdx.x * blockDim.x + threadIdx.x;  // 0 .. N_THREADS_TOTAL-1
    const int lane = threadIdx.x & 31;

    const float w0 = __ldg(w + 0);
    const float w1 = __ldg(w + 1);
    const float w2 = __ldg(w + 2);

    // 4 atoms = 12 floats = 3 coalesced float4 loads + 1 int4 (front-batched, MLP=4)
    const float4 a = xyz4[tid * 3 + 0];
    const float4 b = xyz4[tid * 3 + 1];
    const float4 c = xyz4[tid * 3 + 2];
    const int4  id = ids4[tid];

    // atom k coords: atom0: a.x a.y a.z | atom1: a.w b.x b.y
    //                atom2: b.z b.w c.x | atom3: c.y c.z c.w
    const float t0 = tanh_approx(a.x * w0 + a.y * w1 + a.z * w2);
    const float t1 = tanh_approx(a.w * w0 + b.x * w1 + b.y * w2);
    const float t2 = tanh_approx(b.z * w0 + b.w * w1 + c.x * w2);
    const float t3 = tanh_approx(c.y * w0 + c.z * w1 + c.w * w2);

    const float g0 = 1.0f - t0 * t0;
    const float g1 = 1.0f - t1 * t1;
    const float g2 = 1.0f - t2 * t2;
    const float g3 = 1.0f - t3 * t3;

    grad4[tid * 3 + 0] = make_float4(g0 * w0, g0 * w1, g0 * w2, g1 * w0);
    grad4[tid * 3 + 1] = make_float4(g1 * w1, g1 * w2, g2 * w0, g2 * w1);
    grad4[tid * 3 + 2] = make_float4(g2 * w2, g3 * w0, g3 * w1, g3 * w2);

    // Wait for the zero kernel's writes to energy[] to be complete & visible
    // (everything above is independent of energy, so it overlapped with it).
    cudaGridDependencySynchronize();

    // ---- segment sum of t0..t3 over sorted ids ----
    int   cur = id.x;
    float s   = t0;
    if (id.y == cur) { s += t1; } else { atomicAdd(&energy[cur], s); cur = id.y; s = t1; }
    if (id.z == cur) { s += t2; } else { atomicAdd(&energy[cur], s); cur = id.z; s = t2; }
    if (id.w == cur) { s += t3; } else { atomicAdd(&energy[cur], s); cur = id.w; s = t3; }

    // warp-level segmented reduction (ids sorted => equal-id lanes contiguous)
    #pragma unroll
    for (int off = 1; off < 32; off <<= 1) {
        const float v   = __shfl_down_sync(0xffffffffu, s,   off);
        const int   oid = __shfl_down_sync(0xffffffffu, cur, off);
        if (lane + off < 32 && oid == cur) s += v;
    }
    const int prev = __shfl_up_sync(0xffffffffu, cur, 1);
    if (lane == 0 || prev != cur) {
        atomicAdd(&energy[cur], s);   // run leader flushes whole-run tail sum
    }
}

extern "C" void kernel_launch(void* const* d_in, const int* in_sizes, int n_in,
                              void* d_out, int out_size) {
    const float4* xyz4 = (const float4*)d_in[0];
    const int4*   ids4 = (const int4*)d_in[1];
    const float*  w    = (const float*)d_in[2];

    float* energy = (float*)d_out;                      // [N_MOLS]
    float4* grad4 = (float4*)((float*)d_out + N_MOLS);  // [N_ATOMS*3] floats

    zero_energy_kernel<<<(N_MOLS / 4) / 256, 256>>>((float4*)energy);

    // Launch main kernel with Programmatic Dependent Launch so its prologue
    // (loads/tanh/grad stores) overlaps the zero kernel + launch latency.
    cudaLaunchConfig_t cfg = {};
    cfg.gridDim  = dim3(N_BLOCKS, 1, 1);
    cfg.blockDim = dim3(THREADS, 1, 1);
    cudaLaunchAttribute attrs[1];
    attrs[0].id = cudaLaunchAttributeProgrammaticStreamSerialization;
    attrs[0].val.programmaticStreamSerializationAllowed = 1;
    cfg.attrs    = attrs;
    cfg.numAttrs = 1;
    cudaLaunchKernelEx(&cfg, sumpool_kernel, xyz4, ids4, w, energy, grad4);
}